// round 17
// baseline (speedup 1.0000x reference)
#include <cuda_runtime.h>
#include <cuda_fp16.h>
#include <math.h>
#include <stdint.h>

#define N_NODES 100000
#define N_EDGES 1600000
#define D 128
#define NEG_SLOPE 0.01f
#define SCAN_BLKS ((N_NODES + 1023) / 1024)   // 98

// ---------------- scratch (no allocations allowed) ----------------
__device__ __half2 g_zh[N_NODES * (D / 2)];   // 25.6 MB, z in fp16
__device__ float g_ssrc[N_NODES];
__device__ float g_sdst[N_NODES];
__device__ int   g_deg[N_NODES];
__device__ int   g_off[N_NODES + 1];
__device__ int   g_cur[N_NODES];
__device__ int   g_csr_src[N_EDGES];
__device__ int   g_bsum[128];
__device__ int   g_boff[128];

// pre-swizzled tf32 B tiles: [chunk][n*68 + k], n=0..127, k=0..63
#define KC 64
#define AST 68
__device__ __align__(16) uint32_t g_bt[2][128 * AST];

__device__ __forceinline__ uint32_t f2tf32(float f) {
    uint32_t u;
    asm("cvt.rna.tf32.f32 %0, %1;" : "=r"(u) : "f"(f));
    return u;
}

__device__ __forceinline__ void mma_tf32(float* c, const uint32_t* a,
                                         uint32_t b0, uint32_t b1) {
    asm volatile(
        "mma.sync.aligned.m16n8k8.row.col.f32.tf32.tf32.f32 "
        "{%0,%1,%2,%3}, {%4,%5,%6,%7}, {%8,%9}, {%0,%1,%2,%3};"
        : "+f"(c[0]), "+f"(c[1]), "+f"(c[2]), "+f"(c[3])
        : "r"(a[0]), "r"(a[1]), "r"(a[2]), "r"(a[3]), "r"(b0), "r"(b1));
}

// ---------------- prep: W -> tf32, transposed, padded layout ----------------
__global__ void prep_b_kernel(const float* __restrict__ W) {
    int idx = blockIdx.x * 256 + threadIdx.x;   // 0..16383, idx = kg*128 + n
    if (idx < 16384) {
        int kg = idx >> 7, n = idx & 127;
        g_bt[kg >> 6][n * AST + (kg & 63)] = f2tf32(W[kg * 128 + n]);
    }
}

// ---------------- tf32 mma.sync GEMM: z = h@W, fused scores ----------------
// CTA: 128 rows x 128 cols x K=128 (two 64-chunks). 8 warps, each 32x64.
#define GEMM_SMEM (2 * 128 * AST * 4)   // 69632 B

__global__ __launch_bounds__(256) void gemm_mma_kernel(const float* __restrict__ h,
                                                       const float* __restrict__ attn) {
    extern __shared__ __align__(16) uint32_t smem[];
    uint32_t* As = smem;                  // [128][AST]
    uint32_t* Bs = smem + 128 * AST;      // [128][AST]
    float* sp1 = reinterpret_cast<float*>(smem);          // reused post-mma
    float* sp2 = reinterpret_cast<float*>(smem) + 1152;

    const int t = threadIdx.x;
    const int wid = t >> 5, lane = t & 31;
    const int g = lane >> 2, q = lane & 3;
    const int wr = wid >> 1, wc = wid & 1;
    const int row0 = blockIdx.x * 128;

    float c[2][8][4];
    #pragma unroll
    for (int i = 0; i < 2; i++)
        #pragma unroll
        for (int j = 0; j < 8; j++)
            #pragma unroll
            for (int u = 0; u < 4; u++) c[i][j][u] = 0.f;

    for (int ch = 0; ch < 2; ch++) {
        // A: h rows -> tf32, [r][k] stride AST
        #pragma unroll
        for (int p = t; p < 2048; p += 256) {
            int r = p >> 4, c4 = (p & 15) << 2;
            int grow = row0 + r;
            float4 v = make_float4(0.f, 0.f, 0.f, 0.f);
            if (grow < N_NODES)
                v = *reinterpret_cast<const float4*>(&h[grow * D + ch * KC + c4]);
            uint4 u = make_uint4(f2tf32(v.x), f2tf32(v.y), f2tf32(v.z), f2tf32(v.w));
            *reinterpret_cast<uint4*>(&As[r * AST + c4]) = u;
        }
        // B: linear copy of prepped tile (2176 uint4)
        {
            const uint4* srcB = reinterpret_cast<const uint4*>(g_bt[ch]);
            uint4* dstB = reinterpret_cast<uint4*>(Bs);
            for (int p = t; p < 2176; p += 256) dstB[p] = srcB[p];
        }
        __syncthreads();

        #pragma unroll
        for (int ks = 0; ks < 8; ks++) {
            uint32_t a[2][4];
            #pragma unroll
            for (int i = 0; i < 2; i++) {
                int r = wr * 32 + i * 16 + g;
                a[i][0] = As[r * AST + ks * 8 + q];
                a[i][1] = As[(r + 8) * AST + ks * 8 + q];
                a[i][2] = As[r * AST + ks * 8 + q + 4];
                a[i][3] = As[(r + 8) * AST + ks * 8 + q + 4];
            }
            #pragma unroll
            for (int j = 0; j < 8; j++) {
                int n = wc * 64 + j * 8 + g;
                uint32_t b0 = Bs[n * AST + ks * 8 + q];
                uint32_t b1 = Bs[n * AST + ks * 8 + q + 4];
                mma_tf32(c[0][j], a[0], b0, b1);
                mma_tf32(c[1][j], a[1], b0, b1);
            }
        }
        __syncthreads();
    }

    // epilogue: z (fp16) stores + fused score partials
    #pragma unroll
    for (int i = 0; i < 2; i++) {
        int rA = wr * 32 + i * 16 + g;
        int rB = rA + 8;
        int growA = row0 + rA, growB = row0 + rB;
        float p1a = 0.f, p1b = 0.f, p2a = 0.f, p2b = 0.f;
        #pragma unroll
        for (int j = 0; j < 8; j++) {
            int col = wc * 64 + j * 8 + 2 * q;
            float a1c0 = attn[col], a1c1 = attn[col + 1];
            float a2c0 = attn[D + col], a2c1 = attn[D + col + 1];
            p1a += c[i][j][0] * a1c0 + c[i][j][1] * a1c1;
            p2a += c[i][j][0] * a2c0 + c[i][j][1] * a2c1;
            p1b += c[i][j][2] * a1c0 + c[i][j][3] * a1c1;
            p2b += c[i][j][2] * a2c0 + c[i][j][3] * a2c1;
            if (growA < N_NODES)
                g_zh[growA * 64 + (col >> 1)] = __floats2half2_rn(c[i][j][0], c[i][j][1]);
            if (growB < N_NODES)
                g_zh[growB * 64 + (col >> 1)] = __floats2half2_rn(c[i][j][2], c[i][j][3]);
        }
        sp1[rA * 8 + wc * 4 + q] = p1a;
        sp1[rB * 8 + wc * 4 + q] = p1b;
        sp2[rA * 8 + wc * 4 + q] = p2a;
        sp2[rB * 8 + wc * 4 + q] = p2b;
    }
    __syncthreads();
    if (t < 128) {
        int grow = row0 + t;
        if (grow < N_NODES) {
            float s1 = 0.f, s2 = 0.f;
            #pragma unroll
            for (int k = 0; k < 8; k++) {
                s1 += sp1[t * 8 + k];
                s2 += sp2[t * 8 + k];
            }
            g_ssrc[grow] = s1;
            g_sdst[grow] = s2;
        }
    }
}

// ---------------- CSR build ----------------
// hist: 4 edges/thread via int4 (MLP=4 on the latency-bound atomic stream)
__global__ void hist_kernel(const int* __restrict__ dst) {
    int i = blockIdx.x * blockDim.x + threadIdx.x;
    int base = i * 4;
    if (base + 3 < N_EDGES) {
        int4 v = *reinterpret_cast<const int4*>(&dst[base]);
        atomicAdd(&g_deg[v.x], 1);
        atomicAdd(&g_deg[v.y], 1);
        atomicAdd(&g_deg[v.z], 1);
        atomicAdd(&g_deg[v.w], 1);
    } else {
        for (int k = base; k < N_EDGES; k++) atomicAdd(&g_deg[dst[k]], 1);
    }
}

__global__ __launch_bounds__(1024) void scan1_kernel() {
    __shared__ int wsum[32];
    int t = threadIdx.x, lane = t & 31, wid = t >> 5;
    int i = blockIdx.x * 1024 + t;
    int v = (i < N_NODES) ? g_deg[i] : 0;
    int x = v;
    #pragma unroll
    for (int o = 1; o < 32; o <<= 1) {
        int y = __shfl_up_sync(0xffffffffu, x, o);
        if (lane >= o) x += y;
    }
    if (lane == 31) wsum[wid] = x;
    __syncthreads();
    if (wid == 0) {
        int s = wsum[lane];
        #pragma unroll
        for (int o = 1; o < 32; o <<= 1) {
            int y = __shfl_up_sync(0xffffffffu, s, o);
            if (lane >= o) s += y;
        }
        wsum[lane] = s;
    }
    __syncthreads();
    int prefix = (wid > 0) ? wsum[wid - 1] : 0;
    int incl = x + prefix;
    if (i < N_NODES) g_off[i] = incl - v;
    if (t == 1023) g_bsum[blockIdx.x] = incl;
}

__global__ __launch_bounds__(128) void scan2_kernel() {
    __shared__ int wsum[4];
    int t = threadIdx.x, lane = t & 31, wid = t >> 5;
    int v = (t < SCAN_BLKS) ? g_bsum[t] : 0;
    int x = v;
    #pragma unroll
    for (int o = 1; o < 32; o <<= 1) {
        int y = __shfl_up_sync(0xffffffffu, x, o);
        if (lane >= o) x += y;
    }
    if (lane == 31) wsum[wid] = x;
    __syncthreads();
    int prefix = 0;
    for (int k = 0; k < wid; k++) prefix += wsum[k];
    int incl = x + prefix;
    if (t < SCAN_BLKS) g_boff[t] = incl - v;
}

__global__ void scan3_kernel() {
    int i = blockIdx.x * blockDim.x + threadIdx.x;
    if (i < N_NODES) {
        int v = g_off[i] + g_boff[i >> 10];
        g_off[i] = v;
        g_cur[i] = v;
    }
    if (i == 0) g_off[N_NODES] = N_EDGES;
}

// scatter: 4 edges/thread via int4 loads; stores stay 4B/edge
__global__ void scatter_kernel(const int* __restrict__ src, const int* __restrict__ dst) {
    int i = blockIdx.x * blockDim.x + threadIdx.x;
    int base = i * 4;
    if (base + 3 < N_EDGES) {
        int4 sv = *reinterpret_cast<const int4*>(&src[base]);
        int4 dv = *reinterpret_cast<const int4*>(&dst[base]);
        int p0 = atomicAdd(&g_cur[dv.x], 1);
        int p1 = atomicAdd(&g_cur[dv.y], 1);
        int p2 = atomicAdd(&g_cur[dv.z], 1);
        int p3 = atomicAdd(&g_cur[dv.w], 1);
        g_csr_src[p0] = sv.x;
        g_csr_src[p1] = sv.y;
        g_csr_src[p2] = sv.z;
        g_csr_src[p3] = sv.w;
    } else {
        for (int k = base; k < N_EDGES; k++) {
            int p = atomicAdd(&g_cur[dst[k]], 1);
            g_csr_src[p] = src[k];
        }
    }
}

// ---------------- single-pass aggregation (R5-proven) ----------------
__global__ __launch_bounds__(256) void aggregate_kernel(float* __restrict__ out) {
    int wid  = threadIdx.x >> 5;
    int lane = threadIdx.x & 31;
    int n    = blockIdx.x * 8 + wid;
    if (n >= N_NODES) return;

    int start = g_off[n];
    int end   = g_off[n + 1];
    float sd  = g_sdst[n];

    float4 acc = make_float4(0.f, 0.f, 0.f, 0.f);
    float den_l = 0.f;
    const int h2col = lane * 2;

    for (int base = start; base < end; base += 32) {
        int cnt = end - base;
        if (cnt > 32) cnt = 32;
        int s = 0; float w = 0.f;
        if (lane < cnt) {
            s = g_csr_src[base + lane];
            float e = g_ssrc[s] + sd;
            e = (e > 0.f) ? e : NEG_SLOPE * e;
            w = __expf(e);
            den_l += w;
        }
        #pragma unroll 4
        for (int j = 0; j < cnt; j++) {
            int   sj = __shfl_sync(0xffffffffu, s, j);
            float wj = __shfl_sync(0xffffffffu, w, j);
            uint2 raw = *reinterpret_cast<const uint2*>(&g_zh[sj * (D / 2) + h2col]);
            float2 z0 = __half22float2(*reinterpret_cast<__half2*>(&raw.x));
            float2 z1 = __half22float2(*reinterpret_cast<__half2*>(&raw.y));
            acc.x += wj * z0.x;
            acc.y += wj * z0.y;
            acc.z += wj * z1.x;
            acc.w += wj * z1.y;
        }
    }
    #pragma unroll
    for (int o = 16; o > 0; o >>= 1)
        den_l += __shfl_xor_sync(0xffffffffu, den_l, o);

    float inv = (end > start) ? (1.0f / den_l) : 0.f;
    acc.x *= inv; acc.y *= inv; acc.z *= inv; acc.w *= inv;
    *reinterpret_cast<float4*>(&out[n * D + lane * 4]) = acc;
}

// ---------------- launch: fork CSR chain and GEMM chain onto parallel streams ----------------
extern "C" void kernel_launch(void* const* d_in, const int* in_sizes, int n_in,
                              void* d_out, int out_size) {
    const float* h    = (const float*)d_in[0];
    const float* W    = (const float*)d_in[1];
    const float* attn = (const float*)d_in[2];
    const int* esrc   = (const int*)d_in[3];
    const int* edst   = (const int*)d_in[4];
    float* out        = (float*)d_out;

    (void)in_sizes; (void)n_in; (void)out_size;

    cudaFuncSetAttribute(gemm_mma_kernel,
                         cudaFuncAttributeMaxDynamicSharedMemorySize, GEMM_SMEM);

    cudaStream_t s2;
    cudaStreamCreateWithFlags(&s2, cudaStreamNonBlocking);
    cudaEvent_t eFork, eJoin;
    cudaEventCreateWithFlags(&eFork, cudaEventDisableTiming);
    cudaEventCreateWithFlags(&eJoin, cudaEventDisableTiming);

    void* degPtr = nullptr;
    cudaGetSymbolAddress(&degPtr, g_deg);

    // fork: s2 branches off the origin (capture) stream
    cudaEventRecord(eFork, 0);
    cudaStreamWaitEvent(s2, eFork, 0);

    // branch A (origin stream): GEMM chain — z, scores
    prep_b_kernel<<<64, 256>>>(W);
    gemm_mma_kernel<<<(N_NODES + 127) / 128, 256, GEMM_SMEM>>>(h, attn);

    // branch B (s2): CSR build — independent of z/scores
    cudaMemsetAsync(degPtr, 0, N_NODES * sizeof(int), s2);
    hist_kernel<<<(N_EDGES / 4 + 255) / 256, 256, 0, s2>>>(edst);
    scan1_kernel<<<SCAN_BLKS, 1024, 0, s2>>>();
    scan2_kernel<<<1, 128, 0, s2>>>();
    scan3_kernel<<<(N_NODES + 255) / 256, 256, 0, s2>>>();
    scatter_kernel<<<(N_EDGES / 4 + 255) / 256, 256, 0, s2>>>(esrc, edst);

    // join: origin stream waits for CSR branch, then aggregates
    cudaEventRecord(eJoin, s2);
    cudaStreamWaitEvent(0, eJoin, 0);
    aggregate_kernel<<<(N_NODES + 7) / 8, 256>>>(out);
}